// round 3
// baseline (speedup 1.0000x reference)
#include <cuda_runtime.h>

// PCN_28681791603104 — reduced computation (see R0 analysis):
//   out[0:4096]  = initial S[14]                     (top layer never updated)
//   out[4096:]   = Wg after 10 cycles, where only the layer-13 trajectory matters:
//       P13 = relu(S14) @ Wk13^T   (constant)
//       per cycle: E = S13 - P13 ; G = Wg^T @ E ;
//                  S13 += LR*(relu'(S13) - E)*G ; Wg = LR*E*relu'(S14)^T
//
// R2: latency-bound fix — split-K×2 lane pairs + shfl combine, full unroll,
// 1 barrier/cycle via double-buffered E + triple-buffered Wg.

#define LRV 0.01f
#define NCYC 10

__device__ __forceinline__ unsigned long long pack2(float x) {
    unsigned long long r;
    asm("mov.b64 %0, {%1, %1};" : "=l"(r) : "f"(x));
    return r;
}
__device__ __forceinline__ void fma2(unsigned long long& acc,
                                     unsigned long long a, unsigned long long b) {
    asm("fma.rn.f32x2 %0, %1, %2, %0;" : "+l"(acc) : "l"(a), "l"(b));
}
__device__ __forceinline__ void add2(unsigned long long& a, unsigned long long b) {
    asm("add.rn.f32x2 %0, %0, %1;" : "+l"(a) : "l"(b));
}
__device__ __forceinline__ float2 unpack2(unsigned long long v) {
    float2 f;
    asm("mov.b64 {%0, %1}, %2;" : "=f"(f.x), "=f"(f.y) : "l"(v));
    return f;
}

// smem layout (floats):
//   [0,     4096)   sS14
//   [4096,  8448)   sWkT   (Wk13 transposed, row stride 68)
//   [8448,  16640)  sE[2]  (double buffer)
//   [16640, 28928)  sWg[3] (triple buffer; buffer 2 = initial Wg0)
#define OFF_S14 0
#define OFF_WKT 4096
#define OFF_E   8448
#define OFF_WG  16640
#define SMEM_FLOATS 28928

extern __shared__ float smp[];

// Half-reduction (32 c's) into 8 packed f32x2 accumulators (16 outputs).
// wbase/wstride select W element per c (scalar, broadcast);
// bbase/bstride select a 16-float row chunk per c (4x LDS.128).
__device__ __forceinline__ void gemm_half(const float* __restrict__ wbase, const int wstride,
                                          const float* __restrict__ bbase, const int bstride,
                                          const bool dorelu, unsigned long long acc[8]) {
    #pragma unroll
    for (int cc = 0; cc < 32; cc++) {
        float w = wbase[cc * wstride];
        if (dorelu) w = fmaxf(w, 0.0f);
        unsigned long long wp = pack2(w);
        const ulonglong2* br = (const ulonglong2*)(bbase + cc * bstride);
        ulonglong2 q0 = br[0], q1 = br[1];
        fma2(acc[0], wp, q0.x); fma2(acc[1], wp, q0.y);
        fma2(acc[2], wp, q1.x); fma2(acc[3], wp, q1.y);
        const ulonglong2* br2 = br + 2;
        ulonglong2 q2 = br2[0], q3 = br2[1];
        fma2(acc[4], wp, q2.x); fma2(acc[5], wp, q2.y);
        fma2(acc[6], wp, q3.x); fma2(acc[7], wp, q3.y);
    }
}

// Combine lane pair (xor 1): both lanes end with the full 64-deep sums.
__device__ __forceinline__ void combine16(unsigned long long acc[8], float out[16]) {
    #pragma unroll
    for (int i = 0; i < 8; i++) {
        unsigned long long o = __shfl_xor_sync(0xFFFFFFFFu, acc[i], 1);
        add2(acc[i], o);
        float2 f = unpack2(acc[i]);
        out[2 * i] = f.x; out[2 * i + 1] = f.y;
    }
}

__global__ void __launch_bounds__(512, 1) pcn_kernel(
    const float* __restrict__ S,    // (15,64,64)
    const float* __restrict__ Wk,   // (14,64,64)
    const float* __restrict__ Wg0,  // (64,64)
    float* __restrict__ out,
    int wg_offset)
{
    const int t  = threadIdx.x;
    const int h  = t & 1;                 // c-half owned (0: c<32, 1: c>=32)
    const int b0 = ((t >> 1) & 3) << 4;   // 16-column tile base
    const int a  = t >> 3;                // row (0..63)

    float* sS14 = smp + OFF_S14;
    float* sWkT = smp + OFF_WKT;
    float* sE   = smp + OFF_E;
    float* sWg  = smp + OFF_WG;

    const float* __restrict__ S13g  = S  + 13 * 4096;
    const float* __restrict__ S14g  = S  + 14 * 4096;
    const float* __restrict__ Wk13g = Wk + 13 * 4096;

    // ---- Prologue ----
    #pragma unroll
    for (int kk = 0; kk < 8; kk++) {
        int k = t + kk * 512;
        float v = S14g[k];
        sS14[k] = v;
        out[k]  = v;                       // out[0:4096] = initial S[14]
        sWg[2 * 4096 + k] = Wg0[k];        // buffer 2 = Wg0 (read by cycle 0)
        int o = k >> 6, i = k & 63;
        sWkT[i * 68 + o] = Wk13g[k];
    }

    // Owned S13 tile (16 cols)
    float s13[16];
    #pragma unroll
    for (int j4 = 0; j4 < 4; j4++) {
        float4 v = *(const float4*)(S13g + a * 64 + b0 + j4 * 4);
        s13[j4 * 4 + 0] = v.x; s13[j4 * 4 + 1] = v.y;
        s13[j4 * 4 + 2] = v.z; s13[j4 * 4 + 3] = v.w;
    }

    __syncthreads();

    // mask m[j] = LR * (S14[b0+j][a] > 0)    (relu'(S14)^T, pre-scaled)
    float m[16];
    #pragma unroll
    for (int j = 0; j < 16; j++)
        m[j] = (sS14[(b0 + j) * 64 + a] > 0.0f) ? LRV : 0.0f;

    // ---- P13 = relu(S14) @ Wk13^T (constant, split-K) ----
    float p13[16];
    {
        unsigned long long acc[8] = {0, 0, 0, 0, 0, 0, 0, 0};
        gemm_half(sS14 + a * 64 + h * 32, 1,
                  sWkT + b0 + h * 32 * 68, 68, true, acc);
        combine16(acc, p13);
    }

    // ---- 10 PCN cycles, one barrier each ----
    const bool wr = (wg_offset >= 0);
    #pragma unroll 1
    for (int cyc = 0; cyc < NCYC; cyc++) {
        float* sEw       = sE + (cyc & 1) * 4096;
        float* sWw       = sWg + (cyc % 3) * 4096;        // Wg_{t+1}
        const float* sWr = sWg + ((cyc + 2) % 3) * 4096;  // Wg_t

        // E = S13 - P13 ; Wg_next = E * m. Lane pair splits column stores.
        #pragma unroll
        for (int j4 = 0; j4 < 2; j4++) {
            int jb = h * 8 + j4 * 4;
            float e0 = s13[jb + 0] - p13[jb + 0];
            float e1 = s13[jb + 1] - p13[jb + 1];
            float e2 = s13[jb + 2] - p13[jb + 2];
            float e3 = s13[jb + 3] - p13[jb + 3];
            *(float4*)(sEw + a * 64 + b0 + jb) = make_float4(e0, e1, e2, e3);
            float4 wv = make_float4(e0 * m[jb + 0], e1 * m[jb + 1],
                                    e2 * m[jb + 2], e3 * m[jb + 3]);
            *(float4*)(sWw + a * 64 + b0 + jb) = wv;
            if (cyc == NCYC - 1 && wr)
                *(float4*)(out + wg_offset + a * 64 + b0 + jb) = wv;
        }
        __syncthreads();

        // G[a][b0..b0+15] = sum_c Wg[c][a] * E[c][b0..b0+15]  (split-K)
        unsigned long long acc[8] = {0, 0, 0, 0, 0, 0, 0, 0};
        gemm_half(sWr + a + h * 32 * 64, 64,
                  sEw + b0 + h * 32 * 64, 64, false, acc);
        float g[16];
        combine16(acc, g);

        // S13 += LR * (relu'(S13) - E) * G
        #pragma unroll
        for (int j = 0; j < 16; j++) {
            float ej = s13[j] - p13[j];
            float rp = (s13[j] > 0.0f) ? 1.0f : 0.0f;
            s13[j] = fmaf(LRV * (rp - ej), g[j], s13[j]);
        }
    }
}

extern "C" void kernel_launch(void* const* d_in, const int* in_sizes, int n_in,
                              void* d_out, int out_size) {
    // Identify inputs by element count: S 61440, Wk 57344, Wg 4096.
    const float* S  = nullptr;
    const float* Wk = nullptr;
    const float* Wg = nullptr;
    for (int i = 0; i < n_in; i++) {
        if (in_sizes[i] == 61440)      S  = (const float*)d_in[i];
        else if (in_sizes[i] == 57344) Wk = (const float*)d_in[i];
        else if (in_sizes[i] == 4096)  Wg = (const float*)d_in[i];
    }

    cudaFuncSetAttribute(pcn_kernel,
                         cudaFuncAttributeMaxDynamicSharedMemorySize,
                         SMEM_FLOATS * (int)sizeof(float));

    int wg_off = (out_size >= 8192) ? 4096 : -1;
    pcn_kernel<<<1, 512, SMEM_FLOATS * (int)sizeof(float)>>>(
        S, Wk, Wg, (float*)d_out, wg_off);
}

// round 4
// speedup vs baseline: 5.9405x; 5.9405x over previous
#include <cuda_runtime.h>

// PCN_28681791603104 — reduced computation (R0 analysis, verified rel_err=0):
//   out[0:4096]  = initial S[14]
//   out[4096:]   = Wg after 10 cycles of the self-contained layer-13 recurrence:
//       P13 = relu(S14) @ Wk13^T (constant)
//       E = S13 - P13 ; G = Wg^T @ E ; S13 += LR*(relu'(S13)-E)*G ; Wg' = LR*E*relu'(S14)^T
//
// R3 redesign: the binder is single-SM LDS wavefront throughput (ncu L1 0.6% x148 ~ 89%).
//   - 16 warps, warp = 8 rows x 32 cols, split-K by k-parity across half-warps,
//     shfl_xor(16) combine.
//   - row stride 68 floats => consecutive k rows differ by 4 banks: A (LDS.128,
//     2 distinct 16B) = 1 wf; B (LDS.64, 2x128B contiguous) = 2 wf. Conflict-free.
//   - 2048 wf/GEMM balanced against 2048 FMA-cycles/SMSP/GEMM (f32x2).

#define LRV 0.01f
#define NCYC 10
#define STR 68

__device__ __forceinline__ unsigned long long pack2(float x) {
    unsigned long long r;
    asm("mov.b64 %0, {%1, %1};" : "=l"(r) : "f"(x));
    return r;
}
__device__ __forceinline__ void fma2(unsigned long long& a,
                                     unsigned long long b, unsigned long long c) {
    asm("fma.rn.f32x2 %0, %1, %2, %0;" : "+l"(a) : "l"(b), "l"(c));
}
__device__ __forceinline__ void add2(unsigned long long& a, unsigned long long b) {
    asm("add.rn.f32x2 %0, %0, %1;" : "+l"(a) : "l"(b));
}
__device__ __forceinline__ float2 up2(unsigned long long v) {
    float2 f;
    asm("mov.b64 {%0, %1}, %2;" : "=f"(f.x), "=f"(f.y) : "l"(v));
    return f;
}

// smem: 4 arrays of 64 rows x stride 68 floats
//   sWg [0], sE [1], sA = relu(S14)^T [2], sB = Wk13^T [3]
#define ARR (64 * STR)
#define SMEM_FLOATS (4 * ARR)

extern __shared__ float smp[];

// g[q] (q = rp*2+j) = packed rows (r0+2rp, r0+2rp+1), col c0+j of  A^T-style GEMM:
//   out[a][b] = sum_k A[k][a] * B[k][b],  Abase = sX + r0, Bbase = sY + c0.
// Half-warp kh handles k = 2*jj + kh; shfl_xor(16) combines the two halves.
__device__ __forceinline__ void gemm64(const float* __restrict__ Abase,
                                       const float* __restrict__ Bbase,
                                       int kh, float2 g[8]) {
    unsigned long long acc[8] = {0, 0, 0, 0, 0, 0, 0, 0};
    const float* __restrict__ A = Abase + kh * STR;
    const float* __restrict__ B = Bbase + kh * STR;
    #pragma unroll
    for (int jj = 0; jj < 32; jj++) {
        const ulonglong2* ap = (const ulonglong2*)(A + jj * 2 * STR);
        ulonglong2 a01 = ap[0];          // rows r0..r0+3 as two f32x2 pairs
        ulonglong2 a23 = ap[1];          // rows r0+4..r0+7
        float2 bv = *(const float2*)(B + jj * 2 * STR);
        unsigned long long b0 = pack2(bv.x), b1 = pack2(bv.y);
        fma2(acc[0], a01.x, b0); fma2(acc[1], a01.x, b1);
        fma2(acc[2], a01.y, b0); fma2(acc[3], a01.y, b1);
        fma2(acc[4], a23.x, b0); fma2(acc[5], a23.x, b1);
        fma2(acc[6], a23.y, b0); fma2(acc[7], a23.y, b1);
    }
    #pragma unroll
    for (int i = 0; i < 8; i++) {
        unsigned long long o = __shfl_xor_sync(0xFFFFFFFFu, acc[i], 16);
        add2(acc[i], o);
        g[i] = up2(acc[i]);
    }
}

__global__ void __launch_bounds__(512, 1) pcn_kernel(
    const float* __restrict__ S,    // (15,64,64)
    const float* __restrict__ Wk,   // (14,64,64)
    const float* __restrict__ Wg0,  // (64,64)
    float* __restrict__ out,
    int wg_off)
{
    float* sWg = smp;
    float* sE  = smp + ARR;
    float* sA  = smp + 2 * ARR;     // relu(S14)^T : sA[i*STR + a]
    float* sB  = smp + 3 * ARR;     // Wk13^T      : sB[i*STR + b]

    const float* __restrict__ S13g  = S  + 13 * 4096;
    const float* __restrict__ S14g  = S  + 14 * 4096;
    const float* __restrict__ Wk13g = Wk + 13 * 4096;

    const int t  = threadIdx.x;
    const int w  = t >> 5, l = t & 31;
    const int h  = w >> 3;               // column half (0/1)
    const int r0 = (w & 7) * 8;          // warp's 8 output rows
    const int kh = l >> 4;               // k parity handled by this half-warp
    const int c0 = h * 32 + (l & 15) * 2;// this lane's 2 output cols

    // ---- Prologue: out[0:4096] = S14; build sA, sB, sWg ----
    #pragma unroll
    for (int kk = 0; kk < 8; kk++) {
        int k = t + kk * 512;
        int rr = k >> 6, cc = k & 63;
        float v = S14g[k];
        out[k] = v;
        sA[cc * STR + rr] = fmaxf(v, 0.0f);   // relu(S14)[a=rr][i=cc] transposed
        sB[cc * STR + rr] = Wk13g[k];         // Wk13[b=rr][i=cc] transposed
        sWg[rr * STR + cc] = Wg0[k];          // row-major with stride
    }

    // Packed state: index q = rp*2 + j  ->  (row r0+2rp, row r0+2rp+1) at col c0+j
    float2 s13p[8];
    unsigned mbits = 0;                        // relu'(S14)^T mask bits (2q+component)
    #pragma unroll
    for (int rp = 0; rp < 4; rp++)
        #pragma unroll
        for (int j = 0; j < 2; j++) {
            int q = rp * 2 + j, c = c0 + j;
            s13p[q].x = S13g[(r0 + 2 * rp) * 64 + c];
            s13p[q].y = S13g[(r0 + 2 * rp + 1) * 64 + c];
            if (S14g[c * 64 + r0 + 2 * rp]     > 0.0f) mbits |= 1u << (2 * q);
            if (S14g[c * 64 + r0 + 2 * rp + 1] > 0.0f) mbits |= 1u << (2 * q + 1);
        }
    __syncthreads();

    // ---- P13 (constant) ----
    float2 p13[8];
    gemm64(sA + r0, sB + c0, kh, p13);

    // ---- 10 PCN cycles ----
    float2 wgr[8];
    #pragma unroll 1
    for (int cyc = 0; cyc < NCYC; cyc++) {
        float2 e[8];
        #pragma unroll
        for (int q = 0; q < 8; q++) {
            e[q].x = s13p[q].x - p13[q].x;
            e[q].y = s13p[q].y - p13[q].y;
        }
        __syncthreads();                       // previous GEMM done reading sE/sWg
        if (l < 16) {
            #pragma unroll
            for (int rp = 0; rp < 4; rp++) {
                *(float2*)(sE + (r0 + 2 * rp) * STR + c0) =
                    make_float2(e[rp * 2].x, e[rp * 2 + 1].x);
                *(float2*)(sE + (r0 + 2 * rp + 1) * STR + c0) =
                    make_float2(e[rp * 2].y, e[rp * 2 + 1].y);
                if (cyc > 0) {                 // cycle 0 uses prologue's Wg0
                    *(float2*)(sWg + (r0 + 2 * rp) * STR + c0) =
                        make_float2(wgr[rp * 2].x, wgr[rp * 2 + 1].x);
                    *(float2*)(sWg + (r0 + 2 * rp + 1) * STR + c0) =
                        make_float2(wgr[rp * 2].y, wgr[rp * 2 + 1].y);
                }
            }
        }
        __syncthreads();                       // stores visible

        float2 g[8];
        gemm64(sWg + r0, sE + c0, kh, g);      // G = Wg^T @ E

        #pragma unroll
        for (int q = 0; q < 8; q++) {
            float rx = (s13p[q].x > 0.0f) ? 1.0f : 0.0f;
            float ry = (s13p[q].y > 0.0f) ? 1.0f : 0.0f;
            s13p[q].x = fmaf(LRV * (rx - e[q].x), g[q].x, s13p[q].x);
            s13p[q].y = fmaf(LRV * (ry - e[q].y), g[q].y, s13p[q].y);
            wgr[q].x = (mbits >> (2 * q)     & 1u) ? e[q].x * LRV : 0.0f;
            wgr[q].y = (mbits >> (2 * q + 1) & 1u) ? e[q].y * LRV : 0.0f;
        }
    }

    // ---- Epilogue: Wg_fin = wgr (= LR * E_9 * mask), straight to gmem ----
    if (wg_off >= 0 && l < 16) {
        #pragma unroll
        for (int rp = 0; rp < 4; rp++) {
            *(float2*)(out + wg_off + (r0 + 2 * rp) * 64 + c0) =
                make_float2(wgr[rp * 2].x, wgr[rp * 2 + 1].x);
            *(float2*)(out + wg_off + (r0 + 2 * rp + 1) * 64 + c0) =
                make_float2(wgr[rp * 2].y, wgr[rp * 2 + 1].y);
        }
    }
}

extern "C" void kernel_launch(void* const* d_in, const int* in_sizes, int n_in,
                              void* d_out, int out_size) {
    // Identify inputs by element count: S 61440, Wk 57344, Wg 4096.
    const float* S  = nullptr;
    const float* Wk = nullptr;
    const float* Wg = nullptr;
    for (int i = 0; i < n_in; i++) {
        if (in_sizes[i] == 61440)      S  = (const float*)d_in[i];
        else if (in_sizes[i] == 57344) Wk = (const float*)d_in[i];
        else if (in_sizes[i] == 4096)  Wg = (const float*)d_in[i];
    }

    cudaFuncSetAttribute(pcn_kernel,
                         cudaFuncAttributeMaxDynamicSharedMemorySize,
                         SMEM_FLOATS * (int)sizeof(float));

    int wg_off = (out_size >= 8192) ? 4096 : -1;
    pcn_kernel<<<1, 512, SMEM_FLOATS * (int)sizeof(float)>>>(
        S, Wk, Wg, (float*)d_out, wg_off);
}